// round 12
// baseline (speedup 1.0000x reference)
#include <cuda_runtime.h>
#include <cuda_fp16.h>
#include <cstdint>

#define D 128
#define NE 500000
#define NGRID 200000
#define NMESH 40000
#define LNEPS 1e-5f

#define NB_EDGE 3907
#define NB_GRID 1563
#define NB_MESH 313

// smem byte layout
#define SM_A0   4096
#define ABUF    10240
#define ARS     80
#define SM_HS   24576
#define HRS     272
#define SM_TOTAL 59392

// g_fragB word offsets (uint32): B in mma-fragment order per weight
#define FE1 0
#define FE2 24576
#define FS1 32768
#define FS2 40960
#define FD1 49152
#define FD2 65536
#define FTOT 73728

// setup kernel block ranges
#define SB_CG 25000
#define SB_CM (SB_CG + 5000)
#define SB_ZA (SB_CM + 5000)
#define SB_PF (SB_ZA + 288)
#define SB_TOT SB_PF

__device__ __align__(16) float    g_agg[(size_t)NMESH * D];
__device__ __align__(16) uint32_t g_fragB[FTOT];
__device__ __align__(16) __half   grid_h[(size_t)NGRID * D];
__device__ __align__(16) __half   mesh_h[(size_t)NMESH * D];

__device__ __forceinline__ float silu_f(float x) { return x / (1.0f + __expf(-x)); }
__device__ __forceinline__ uint32_t pack2(float x, float y) {
    __half2 h = __floats2half2_rn(x, y);
    return *reinterpret_cast<uint32_t*>(&h);
}
__device__ __forceinline__ void mma16(float* c, const uint32_t* a, const uint32_t* b) {
    asm volatile(
        "mma.sync.aligned.m16n8k16.row.col.f32.f16.f16.f32 "
        "{%0,%1,%2,%3}, {%4,%5,%6,%7}, {%8,%9}, {%0,%1,%2,%3};"
        : "+f"(c[0]), "+f"(c[1]), "+f"(c[2]), "+f"(c[3])
        : "r"(a[0]), "r"(a[1]), "r"(a[2]), "r"(a[3]), "r"(b[0]), "r"(b[1]));
}
__device__ __forceinline__ void ldsm4(uint32_t* r, uint32_t saddr) {
    asm volatile("ldmatrix.sync.aligned.m8n8.x4.shared.b16 {%0,%1,%2,%3}, [%4];"
                 : "=r"(r[0]), "=r"(r[1]), "=r"(r[2]), "=r"(r[3]) : "r"(saddr));
}

// ---------------- fused setup ----------------
__global__ void setup_kernel(const float* __restrict__ grid, const float* __restrict__ mesh,
                             const float* __restrict__ ew1, const float* __restrict__ ew2,
                             const float* __restrict__ sw1, const float* __restrict__ sw2,
                             const float* __restrict__ dw1, const float* __restrict__ dw2) {
    const int b = blockIdx.x;
    const int t = threadIdx.x;
    if (b < SB_CG) {
        int i = b * 256 + t;
        float4 v = ((const float4*)grid)[i];
        uint2 o; o.x = pack2(v.x, v.y); o.y = pack2(v.z, v.w);
        ((uint2*)grid_h)[i] = o;
    } else if (b < SB_CM) {
        int i = (b - SB_CG) * 256 + t;
        float4 v = ((const float4*)mesh)[i];
        uint2 o; o.x = pack2(v.x, v.y); o.y = pack2(v.z, v.w);
        ((uint2*)mesh_h)[i] = o;
    } else if (b < SB_ZA) {
        int i = (b - SB_CM) * 256 + t;
        ((float4*)g_agg)[i] = make_float4(0.f, 0.f, 0.f, 0.f);
    } else {
        int i = (b - SB_ZA) * 256 + t;
        if (i >= FTOT) return;
        const float* src; int off;
        if (i < FE2)      { src = ew1; off = FE1; }
        else if (i < FS1) { src = ew2; off = FE2; }
        else if (i < FS2) { src = sw1; off = FS1; }
        else if (i < FD1) { src = sw2; off = FS2; }
        else if (i < FD2) { src = dw1; off = FD1; }
        else              { src = dw2; off = FD2; }
        int j = i - off;
        int blk = j >> 6, r = j & 63;
        int ln = r >> 1, jw = r & 1;
        int c16 = blk >> 4, nt = blk & 15;
        int n  = nt * 8 + (ln >> 2);
        int k0 = c16 * 16 + jw * 8 + 2 * (ln & 3);
        g_fragB[i] = pack2(src[(size_t)k0 * 128 + n], src[(size_t)(k0 + 1) * 128 + n]);
    }
}

// ---------------- fused MLP body ----------------
template<int NSEG, int NF, int MODE>
__device__ __forceinline__
void mlp_body(int bid, char* smem,
              const float* __restrict__ segF,
              const int* __restrict__ idx1, const int* __restrict__ idx2,
              int M, int wt1_off, int wt2_off,
              const float* __restrict__ b1, const float* __restrict__ b2,
              const float* __restrict__ gam, const float* __restrict__ bet,
              const float* __restrict__ resid, float* __restrict__ outp,
              const int* __restrict__ scat)
{
    const uint32_t sbase = (uint32_t)__cvta_generic_to_shared(smem);

    const int t    = threadIdx.x;
    const int lane = t & 31;
    const int warp = t >> 5;
    const int wm   = warp & 3;
    const int wn   = warp >> 2;
    const int m0   = bid * 128;
    const int rm   = wm * 32;
    const int g    = lane >> 2;
    const int c4   = lane & 3;
    const int cb0  = wn * 64 + 2 * c4;

    const uint32_t a_geo = (uint32_t)((rm + (lane & 15)) * ARS + (lane >> 4) * 16);
    const uint32_t h_geo = (uint32_t)((rm + (lane & 15)) * HRS + (lane >> 4) * 16);

    const int ma = min(m0 + (t >> 1), M - 1);
    const float* sF = (MODE == 1) ? (const float*)g_agg : segF;
    const float* rpF = (NF > 0) ? sF + (size_t)ma * D : nullptr;
    const __half* hA = (MODE == 1) ? mesh_h : grid_h;
    const int iH0 = (MODE == 0) ? idx1[ma] : ma;
    const __half* rpH0 = hA + (size_t)iH0 * D;
    const __half* rpH1 = (NSEG == 3) ? mesh_h + (size_t)idx2[ma] * D : nullptr;

    const uint2* w1f = (const uint2*)(g_fragB + wt1_off);
    const uint2* w2f = (const uint2*)(g_fragB + wt2_off);

    float acc[2][8][4];
#pragma unroll
    for (int mt = 0; mt < 2; ++mt)
#pragma unroll
        for (int jt = 0; jt < 8; ++jt)
#pragma unroll
            for (int q = 0; q < 4; ++q) acc[mt][jt][q] = 0.f;

    float4 fR[4];
    uint4  hU[2];
    auto ldF = [&](int c) {
        const float4* p = (const float4*)(rpF + (c & 3) * 32 + (t & 1) * 16);
        fR[0] = p[0]; fR[1] = p[1]; fR[2] = p[2]; fR[3] = p[3];
    };
    auto stF = [&](int slot) {
        char* dst = smem + SM_A0 + slot * ABUF + (t >> 1) * ARS + (t & 1) * 32;
        uint4 u0, u1;
        u0.x = pack2(fR[0].x, fR[0].y); u0.y = pack2(fR[0].z, fR[0].w);
        u0.z = pack2(fR[1].x, fR[1].y); u0.w = pack2(fR[1].z, fR[1].w);
        u1.x = pack2(fR[2].x, fR[2].y); u1.y = pack2(fR[2].z, fR[2].w);
        u1.z = pack2(fR[3].x, fR[3].y); u1.w = pack2(fR[3].z, fR[3].w);
        *(uint4*)dst = u0;
        *(uint4*)(dst + 16) = u1;
    };
    auto ldH = [&](int c) {
        const __half* src = ((c >> 2) == NF) ? rpH0 : rpH1;
        const uint4* p = (const uint4*)((const char*)src + (c & 3) * 64 + (t & 1) * 32);
        hU[0] = p[0]; hU[1] = p[1];
    };
    auto stH = [&](int slot) {
        char* dst = smem + SM_A0 + slot * ABUF + (t >> 1) * ARS + (t & 1) * 32;
        *(uint4*)dst = hU[0];
        *(uint4*)(dst + 16) = hU[1];
    };

    auto compute = [&](uint32_t abase, uint32_t astep, const uint2* __restrict__ bw, int c) {
#pragma unroll
        for (int ks = 0; ks < 2; ++ks) {
            uint32_t a0f[4], a1f[4];
            ldsm4(a0f, abase + ks * 32);
            ldsm4(a1f, abase + astep + ks * 32);
            const uint2* bt = bw + ((((2 * c + ks) * 16) + wn * 8) << 5) + lane;
#pragma unroll
            for (int p = 0; p < 4; ++p) {
                uint2 B0 = bt[(2 * p) << 5];
                uint2 B1 = bt[(2 * p + 1) << 5];
                mma16(acc[0][2 * p],     a0f, &B0.x);
                mma16(acc[0][2 * p + 1], a0f, &B1.x);
                mma16(acc[1][2 * p],     a1f, &B0.x);
                mma16(acc[1][2 * p + 1], a1f, &B1.x);
            }
        }
    };

    // ---------------- GEMM1 ----------------
    const int NC1 = NSEG * 4;
    if (NF > 0) { ldF(0); stF(0); }
    else        { ldH(0); stH(0); }
    __syncthreads();

    for (int c = 0; c < NC1; ++c) {
        const bool pf  = (c + 1 < NC1);
        const bool nxF = (NF > 0) && (((c + 1) >> 2) < NF);
        if (pf) { if (nxF) ldF(c + 1); else ldH(c + 1); }
        compute(sbase + SM_A0 + (c & 1) * ABUF + a_geo, 16 * ARS, w1f, c);
        if (pf) { if (nxF) stF((c + 1) & 1); else stH((c + 1) & 1); }
        __syncthreads();
    }

    // epilogue1: bias + SiLU -> half h into Hs
    {
        float2 b1r[8];
#pragma unroll
        for (int jt = 0; jt < 8; ++jt) b1r[jt] = *(const float2*)(b1 + cb0 + jt * 8);
#pragma unroll
        for (int mt = 0; mt < 2; ++mt) {
            const int r0 = rm + mt * 16 + g;
#pragma unroll
            for (int jt = 0; jt < 8; ++jt) {
                const int cb = cb0 + jt * 8;
                float h0 = silu_f(acc[mt][jt][0] + b1r[jt].x);
                float h1 = silu_f(acc[mt][jt][1] + b1r[jt].y);
                float h2 = silu_f(acc[mt][jt][2] + b1r[jt].x);
                float h3 = silu_f(acc[mt][jt][3] + b1r[jt].y);
                *(uint32_t*)(smem + SM_HS + r0 * HRS + cb * 2)       = pack2(h0, h1);
                *(uint32_t*)(smem + SM_HS + (r0 + 8) * HRS + cb * 2) = pack2(h2, h3);
            }
        }
    }
#pragma unroll
    for (int mt = 0; mt < 2; ++mt)
#pragma unroll
        for (int jt = 0; jt < 8; ++jt)
#pragma unroll
            for (int q = 0; q < 4; ++q) acc[mt][jt][q] = 0.f;
    __syncthreads();

    // ---------------- GEMM2 (no barriers, B from global) ----------------
#pragma unroll
    for (int c = 0; c < 4; ++c)
        compute(sbase + SM_HS + h_geo + c * 64, 16 * HRS, w2f, c);

    // ---------------- epilogue2: bias + register LN + paired float4 out/scatter ----------------
    {
        float2 b2r[8], gmr[8], btr[8];
#pragma unroll
        for (int jt = 0; jt < 8; ++jt) {
            b2r[jt] = *(const float2*)(b2 + cb0 + jt * 8);
            gmr[jt] = *(const float2*)(gam + cb0 + jt * 8);
            btr[jt] = *(const float2*)(bet + cb0 + jt * 8);
        }
        float s[2][2]  = {{0.f, 0.f}, {0.f, 0.f}};
        float ss[2][2] = {{0.f, 0.f}, {0.f, 0.f}};
#pragma unroll
        for (int mt = 0; mt < 2; ++mt)
#pragma unroll
            for (int jt = 0; jt < 8; ++jt) {
                float v0 = acc[mt][jt][0] + b2r[jt].x;
                float v1 = acc[mt][jt][1] + b2r[jt].y;
                float v2 = acc[mt][jt][2] + b2r[jt].x;
                float v3 = acc[mt][jt][3] + b2r[jt].y;
                s[mt][0] += v0 + v1;  ss[mt][0] += v0 * v0 + v1 * v1;
                s[mt][1] += v2 + v3;  ss[mt][1] += v2 * v2 + v3 * v3;
            }
#pragma unroll
        for (int off = 1; off <= 2; off <<= 1)
#pragma unroll
            for (int mt = 0; mt < 2; ++mt)
#pragma unroll
                for (int h = 0; h < 2; ++h) {
                    s[mt][h]  += __shfl_xor_sync(0xffffffffu, s[mt][h], off);
                    ss[mt][h] += __shfl_xor_sync(0xffffffffu, ss[mt][h], off);
                }
        float2* part = (float2*)smem;
        if (c4 == 0) {
#pragma unroll
            for (int mt = 0; mt < 2; ++mt)
#pragma unroll
                for (int h = 0; h < 2; ++h)
                    part[wn * 128 + rm + mt * 16 + g + h * 8] = make_float2(s[mt][h], ss[mt][h]);
        }
        __syncthreads();

        // each lane handles ONE mt (even c4 -> mt=0, odd c4 -> mt=1) with float4 ops
        const int myMt  = c4 & 1;
        const int cbase = wn * 64 + 2 * (c4 & 2);   // float4-aligned col base (0 or 4 within oct)
#pragma unroll
        for (int h = 0; h < 2; ++h) {
            // per-row LN stats for BOTH mt (uniform per pair)
            float mu[2], rs[2];
            int mrow[2];
#pragma unroll
            for (int mt = 0; mt < 2; ++mt) {
                const int R = rm + mt * 16 + g + h * 8;
                mrow[mt] = m0 + R;
                float2 pa = part[R], pb = part[128 + R];
                mu[mt] = (pa.x + pb.x) * (1.0f / 128.0f);
                float var = (pa.y + pb.y) * (1.0f / 128.0f) - mu[mt] * mu[mt];
                rs[mt] = rsqrtf(var + LNEPS);
            }
            const int m = mrow[myMt];
            const bool valid = (m < M);
            float* aggp = (MODE == 0 && valid) ? g_agg + (size_t)scat[m] * D : nullptr;
            const float* rvp = (MODE != 0) ? resid + (size_t)m * D : nullptr;
            float* op = (MODE != 0) ? outp + (size_t)m * D : nullptr;
#pragma unroll
            for (int jt = 0; jt < 8; ++jt) {
                // build exchanged float4 for my mt
                float4 f4;
#pragma unroll
                for (int mt = 0; mt < 2; ++mt) {
                    float v0 = acc[mt][jt][2 * h]     + b2r[jt].x;
                    float v1 = acc[mt][jt][2 * h + 1] + b2r[jt].y;
                    float o0 = (v0 - mu[mt]) * rs[mt] * gmr[jt].x + btr[jt].x;
                    float o1 = (v1 - mu[mt]) * rs[mt] * gmr[jt].y + btr[jt].y;
                    float p0 = __shfl_xor_sync(0xffffffffu, o0, 1);
                    float p1 = __shfl_xor_sync(0xffffffffu, o1, 1);
                    if (mt == myMt) {
                        if (c4 & 1) f4 = make_float4(p0, p1, o0, o1);
                        else        f4 = make_float4(o0, o1, p0, p1);
                    }
                }
                if (valid) {
                    const int cb = cbase + jt * 8;
                    if (MODE == 0) {
                        atomicAdd((float4*)(aggp + cb), f4);
                    } else {
                        float4 rr = *(const float4*)(rvp + cb);
                        *(float4*)(op + cb) = make_float4(f4.x + rr.x, f4.y + rr.y,
                                                          f4.z + rr.z, f4.w + rr.w);
                    }
                }
            }
        }
    }
}

// edge blocks [0, NB_EDGE), grid-node blocks [NB_EDGE, NB_EDGE+NB_GRID)
__global__ __launch_bounds__(256, 2)
void edge_grid_kernel(const float* __restrict__ g2m,
                      const int* __restrict__ src, const int* __restrict__ dst,
                      const float* __restrict__ eb1, const float* __restrict__ eb2,
                      const float* __restrict__ eg,  const float* __restrict__ ebt,
                      const float* __restrict__ sb1, const float* __restrict__ sb2,
                      const float* __restrict__ sg,  const float* __restrict__ sbt,
                      const float* __restrict__ gridf, float* __restrict__ grid_out)
{
    extern __shared__ char smem[];
    const int b = blockIdx.x;
    if (b < NB_EDGE) {
        mlp_body<3,1,0>(b, smem, g2m, src, dst, NE, FE1, FE2,
                        eb1, eb2, eg, ebt, nullptr, nullptr, dst);
    } else {
        mlp_body<1,0,2>(b - NB_EDGE, smem, nullptr, nullptr, nullptr, NGRID, FS1, FS2,
                        sb1, sb2, sg, sbt, gridf, grid_out, nullptr);
    }
}

__global__ __launch_bounds__(256, 2)
void mesh_kernel(const float* __restrict__ db1, const float* __restrict__ db2,
                 const float* __restrict__ dg,  const float* __restrict__ dbt,
                 const float* __restrict__ mesh, float* __restrict__ mesh_out)
{
    extern __shared__ char smem[];
    mlp_body<2,1,1>(blockIdx.x, smem, nullptr, nullptr, nullptr, NMESH, FD1, FD2,
                    db1, db2, dg, dbt, mesh, mesh_out, nullptr);
}

extern "C" void kernel_launch(void* const* d_in, const int* in_sizes, int n_in,
                              void* d_out, int out_size) {
    const float* g2m  = (const float*)d_in[0];
    const float* grid = (const float*)d_in[1];
    const float* mesh = (const float*)d_in[2];
    const int*   src  = (const int*)d_in[3];
    const int*   dst  = (const int*)d_in[4];
    const float* ew1 = (const float*)d_in[5];
    const float* eb1 = (const float*)d_in[6];
    const float* ew2 = (const float*)d_in[7];
    const float* eb2 = (const float*)d_in[8];
    const float* eg  = (const float*)d_in[9];
    const float* ebt = (const float*)d_in[10];
    const float* sw1 = (const float*)d_in[11];
    const float* sb1 = (const float*)d_in[12];
    const float* sw2 = (const float*)d_in[13];
    const float* sb2 = (const float*)d_in[14];
    const float* sg  = (const float*)d_in[15];
    const float* sbt = (const float*)d_in[16];
    const float* dw1 = (const float*)d_in[17];
    const float* db1 = (const float*)d_in[18];
    const float* dw2 = (const float*)d_in[19];
    const float* db2 = (const float*)d_in[20];
    const float* dg  = (const float*)d_in[21];
    const float* dbt = (const float*)d_in[22];

    float* grid_out = (float*)d_out;                  // [NGRID, D]
    float* mesh_out = grid_out + (size_t)NGRID * D;   // [NMESH, D]

    cudaFuncSetAttribute(edge_grid_kernel, cudaFuncAttributeMaxDynamicSharedMemorySize, SM_TOTAL);
    cudaFuncSetAttribute(mesh_kernel, cudaFuncAttributeMaxDynamicSharedMemorySize, SM_TOTAL);

    setup_kernel<<<SB_TOT, 256>>>(grid, mesh, ew1, ew2, sw1, sw2, dw1, dw2);

    edge_grid_kernel<<<NB_EDGE + NB_GRID, 256, SM_TOTAL>>>(
        g2m, src, dst, eb1, eb2, eg, ebt, sb1, sb2, sg, sbt, grid, grid_out);

    mesh_kernel<<<NB_MESH, 256, SM_TOTAL>>>(db1, db2, dg, dbt, mesh, mesh_out);
}